// round 13
// baseline (speedup 1.0000x reference)
#include <cuda_runtime.h>
#include <cstdint>
#include <math.h>

// ---------------- problem constants ----------------
#define BATCH 4
#define HH 64
#define WW 64
#define DIM 768
#define NHEAD 12
#define HD 64
#define MLP 3072
#define WS 14
#define NT 196              // tokens per window (14*14)
#define NWIN 100            // windows: 4 * 5 * 5
#define TOK (NWIN*NT)       // 19600 window tokens
#define BHD (NWIN*NHEAD)    // 1200 (window, head) pairs
#define MTOK (BATCH*HH*WW)  // 16384 image tokens

// ---------------- device scratch (no dynamic alloc allowed) ----------------
__device__ int8_t g_qa  [TOK*DIM];        // quantized LN1 output (windowed), scale a4
__device__ int8_t g_wqkv[3*DIM*DIM];      // quantized weights
__device__ int8_t g_wproj[DIM*DIM];
__device__ int8_t g_wl1 [MLP*DIM];
__device__ int8_t g_wl2 [DIM*MLP];
__device__ int8_t g_q8  [BHD*NT*HD];      // [bh][tok][d], scale a0
__device__ int8_t g_k8  [BHD*NT*HD];      // [bh][tok][d], scale a1
__device__ int8_t g_v8  [BHD*NT*HD];      // [bh][tok][d], scale a2 (row-major)
__device__ int8_t g_ao8 [TOK*DIM];        // attention output, quantized scale a5
__device__ float  g_x2  [MTOK*DIM];       // x + attn branch (residual 1)
__device__ int8_t g_y8  [MTOK*DIM];       // quantized LN2 output, scale a6
__device__ int8_t g_g8  [MTOK*MLP];       // quantized GELU output, scale a7

// ---------------- helpers ----------------
__device__ __forceinline__ int qint(float x, float inv) {
    float r = rintf(x * inv);
    r = fminf(fmaxf(r, -128.f), 127.f);
    return (int)r;
}

__device__ __forceinline__ uint32_t pack4(int a, int b, int c, int d) {
    return (uint32_t)(uint8_t)(int8_t)a | ((uint32_t)(uint8_t)(int8_t)b << 8)
         | ((uint32_t)(uint8_t)(int8_t)c << 16) | ((uint32_t)(uint8_t)(int8_t)d << 24);
}

__device__ __forceinline__ void ldsm4(uint32_t& r0, uint32_t& r1, uint32_t& r2, uint32_t& r3,
                                      uint32_t addr) {
    asm volatile("ldmatrix.sync.aligned.m8n8.x4.shared.b16 {%0,%1,%2,%3}, [%4];"
                 : "=r"(r0), "=r"(r1), "=r"(r2), "=r"(r3) : "r"(addr));
}

__device__ __forceinline__ void mma_s8(int* c, const uint32_t* a, uint32_t b0, uint32_t b1) {
    asm volatile("mma.sync.aligned.m16n8k32.row.col.s32.s8.s8.s32 "
                 "{%0,%1,%2,%3}, {%4,%5,%6,%7}, {%8,%9}, {%0,%1,%2,%3};"
                 : "+r"(c[0]), "+r"(c[1]), "+r"(c[2]), "+r"(c[3])
                 : "r"(a[0]), "r"(a[1]), "r"(a[2]), "r"(a[3]), "r"(b0), "r"(b1));
}

__device__ __forceinline__ void cpasync16(uint32_t dst, const void* src) {
    asm volatile("cp.async.cg.shared.global [%0], [%1], 16;" :: "r"(dst), "l"(src) : "memory");
}

// swizzled smem offset for a row-of-64B tile; c = 16B chunk 0..3
__device__ __forceinline__ uint32_t swz(int row, int c) {
    return (uint32_t)(row * 64 + ((c ^ ((row >> 1) & 3)) << 4));
}

// ---------------- weight quantization ----------------
__global__ __launch_bounds__(256) void quantw_a(const float* __restrict__ qkvw,
                                                const float* __restrict__ projw,
                                                const float* __restrict__ wS) {
    const int B0 = 442368, B1 = 589824;
    float i0 = 1.f / wS[0], i1 = 1.f / wS[1];
    for (int idx = blockIdx.x * blockDim.x + threadIdx.x; idx < B1; idx += gridDim.x * blockDim.x) {
        const float* src; uint32_t* dst; float inv; int off;
        if (idx < B0) { off = idx;      src = qkvw;  dst = (uint32_t*)g_wqkv;  inv = i0; }
        else          { off = idx - B0; src = projw; dst = (uint32_t*)g_wproj; inv = i1; }
        float4 v = ((const float4*)src)[off];
        dst[off] = pack4(qint(v.x, inv), qint(v.y, inv), qint(v.z, inv), qint(v.w, inv));
    }
}

__global__ __launch_bounds__(256) void quantw_b(const float* __restrict__ l1w,
                                                const float* __restrict__ l2w,
                                                const float* __restrict__ wS) {
    const int B0 = 589824, B1 = 1179648;
    float i2 = 1.f / wS[2], i3 = 1.f / wS[3];
    for (int idx = blockIdx.x * blockDim.x + threadIdx.x; idx < B1; idx += gridDim.x * blockDim.x) {
        const float* src; uint32_t* dst; float inv; int off;
        if (idx < B0) { off = idx;      src = l1w; dst = (uint32_t*)g_wl1; inv = i2; }
        else          { off = idx - B0; src = l2w; dst = (uint32_t*)g_wl2; inv = i3; }
        float4 v = ((const float4*)src)[off];
        dst[off] = pack4(qint(v.x, inv), qint(v.y, inv), qint(v.z, inv), qint(v.w, inv));
    }
}

// ---------------- warp-per-row LayerNorm + quantize ----------------
template <int MODE>
__global__ __launch_bounds__(256) void ln_kernel(const float* __restrict__ x,
                                                 const float* __restrict__ w,
                                                 const float* __restrict__ b,
                                                 const float* __restrict__ actS) {
    int row = blockIdx.x * 8 + (threadIdx.x >> 5);
    int lane = threadIdx.x & 31;
    const float* src;
    uint32_t* orow;
    if (MODE == 0) {
        if (row >= TOK) return;
        int bw = row / NT, tok = row % NT;
        int bi = bw / 25, wy = (bw % 25) / 5, wx = bw % 5;
        int gy = wy * WS + tok / WS, gx = wx * WS + tok % WS;
        orow = (uint32_t*)(g_qa + (size_t)row * DIM);
        if (gy >= HH || gx >= WW) {
#pragma unroll
            for (int i = 0; i < 6; i++) orow[lane + 32 * i] = 0;
            return;
        }
        src = x + (((size_t)bi * HH + gy) * WW + gx) * DIM;
    } else {
        if (row >= MTOK) return;
        src = g_x2 + (size_t)row * DIM;
        orow = (uint32_t*)(g_y8 + (size_t)row * DIM);
    }

    const float4* s4 = (const float4*)src;
    float4 v[6];
    float sum = 0.f;
#pragma unroll
    for (int i = 0; i < 6; i++) {
        v[i] = s4[lane + 32 * i];
        sum += v[i].x + v[i].y + v[i].z + v[i].w;
    }
#pragma unroll
    for (int o = 16; o > 0; o >>= 1) sum += __shfl_xor_sync(0xffffffff, sum, o);
    float mu = sum * (1.f / DIM);
    float s2 = 0.f;
#pragma unroll
    for (int i = 0; i < 6; i++) {
        float dx = v[i].x - mu, dy = v[i].y - mu, dz = v[i].z - mu, dw = v[i].w - mu;
        s2 += dx * dx + dy * dy + dz * dz + dw * dw;
    }
#pragma unroll
    for (int o = 16; o > 0; o >>= 1) s2 += __shfl_xor_sync(0xffffffff, s2, o);
    float rstd = rsqrtf(s2 * (1.f / DIM) + 1e-6f);
    float inv = 1.f / actS[MODE == 0 ? 4 : 6];
    const float4* w4 = (const float4*)w;
    const float4* b4 = (const float4*)b;
#pragma unroll
    for (int i = 0; i < 6; i++) {
        float4 wv = w4[lane + 32 * i], bv = b4[lane + 32 * i];
        orow[lane + 32 * i] = pack4(qint((v[i].x - mu) * rstd * wv.x + bv.x, inv),
                                    qint((v[i].y - mu) * rstd * wv.y + bv.y, inv),
                                    qint((v[i].z - mu) * rstd * wv.z + bv.z, inv),
                                    qint((v[i].w - mu) * rstd * wv.w + bv.w, inv));
    }
}

// ---------------- two-flavor GEMM: C = A @ B^T ----------------
// 128x128x64B tiles, 256 threads. blockIdx.y % 5 < 3 -> IMMA flavor (tensor pipe),
// else dp4a flavor (ALU pipe). Co-resident blocks of different flavors use
// disjoint execution pipes -> additive throughput. Shared loader + staged epilogue.
template <int EPI>
__global__ __launch_bounds__(256, 2) void gemm_tf(int M, int N, int K,
                                                  const float* __restrict__ actS,
                                                  const float* __restrict__ wS,
                                                  const float* __restrict__ bias,
                                                  const float* __restrict__ xin,
                                                  float* __restrict__ outf) {
    const int8_t* Aptr;
    const int8_t* Bptr;
    if (EPI == 0)      { Aptr = g_qa;  Bptr = g_wqkv;  }
    else if (EPI == 1) { Aptr = g_ao8; Bptr = g_wproj; }
    else if (EPI == 2) { Aptr = g_y8;  Bptr = g_wl1;   }
    else               { Aptr = g_g8;  Bptr = g_wl2;   }

    extern __shared__ int8_t dsm_raw[];
    uint32_t raw32 = (uint32_t)__cvta_generic_to_shared(dsm_raw);
    uint32_t sbase = (raw32 + 1023u) & ~1023u;
    int8_t* smem_gen = dsm_raw + (sbase - raw32);
    uint32_t sA[2] = { sbase,          sbase + 8192  };
    uint32_t sB[2] = { sbase + 16384,  sbase + 24576 };

    int tid = threadIdx.x;
    int warp = tid >> 5, lane = tid & 31;
    int m0 = blockIdx.y * 128, n0 = blockIdx.x * 128;
    bool imma_flavor = (blockIdx.y % 5) < 3;

    const int NSt = K >> 6;                 // stages of 64 bytes

    auto load_stage = [&](int s, int k0) {
#pragma unroll
        for (int i = 0; i < 2; i++) {
            int idx = tid + i * 256;        // 0..511
            int row = idx >> 2, c = idx & 3;
            int rg = m0 + row; if (rg >= M) rg = M - 1;   // clamp; bad rows unused
            cpasync16(sA[s] + swz(row, c), Aptr + (size_t)rg * K + k0 + c * 16);
            cpasync16(sB[s] + swz(row, c), Bptr + (size_t)(n0 + row) * K + k0 + c * 16);
        }
        asm volatile("cp.async.commit_group;" ::: "memory");
    };

    int* Cst = (int*)smem_gen;   // 64KB C staging (reused post-mainloop)

    if (imma_flavor) {
        // ================= IMMA flavor (verified R8 mainloop) =================
        int wm = (warp & 1) * 64;
        int wn = (warp >> 1) * 32;
        int acc[4][4][4];
#pragma unroll
        for (int mi = 0; mi < 4; mi++)
#pragma unroll
            for (int ni = 0; ni < 4; ni++)
#pragma unroll
                for (int r = 0; r < 4; r++) acc[mi][ni][r] = 0;

        load_stage(0, 0);
        for (int st = 0; st < NSt; st++) {
            if (st + 1 < NSt) {
                load_stage((st + 1) & 1, (st + 1) << 6);
                asm volatile("cp.async.wait_group 1;" ::: "memory");
            } else {
                asm volatile("cp.async.wait_group 0;" ::: "memory");
            }
            __syncthreads();
            int s = st & 1;
#pragma unroll
            for (int ks = 0; ks < 2; ks++) {
                uint32_t a[4][4];
#pragma unroll
                for (int mi = 0; mi < 4; mi++) {
                    int r = wm + mi * 16 + (lane & 15);
                    int c = ks * 2 + (lane >> 4);
                    ldsm4(a[mi][0], a[mi][1], a[mi][2], a[mi][3], sA[s] + swz(r, c));
                }
                uint32_t bb[2][4];
#pragma unroll
                for (int nj = 0; nj < 2; nj++) {
                    int rn = wn + nj * 16 + (lane & 7) + ((lane >> 1) & 8);
                    int c = ks * 2 + ((lane >> 3) & 1);
                    ldsm4(bb[nj][0], bb[nj][1], bb[nj][2], bb[nj][3], sB[s] + swz(rn, c));
                }
#pragma unroll
                for (int mi = 0; mi < 4; mi++)
#pragma unroll
                    for (int ni = 0; ni < 4; ni++)
                        mma_s8(acc[mi][ni], a[mi], bb[ni >> 1][(ni & 1) * 2], bb[ni >> 1][(ni & 1) * 2 + 1]);
            }
            __syncthreads();
        }
        // stage C into smem
#pragma unroll
        for (int mi = 0; mi < 4; mi++) {
            int r = wm + mi * 16 + (lane >> 2);
#pragma unroll
            for (int ni = 0; ni < 4; ni++) {
                int c = wn + ni * 8 + (lane & 3) * 2;
                int chs = (((c >> 2) ^ (r & 7)) << 2) | (c & 3);
                *(int2*)&Cst[r * 128 + chs]       = make_int2(acc[mi][ni][0], acc[mi][ni][1]);
                *(int2*)&Cst[(r + 8) * 128 + chs] = make_int2(acc[mi][ni][2], acc[mi][ni][3]);
            }
        }
        __syncthreads();
    } else {
        // ================= dp4a flavor (ALU pipe) =================
        // thread: rows rbase..rbase+7 (rbase = warp*16 + (lane>>4)*8), cols (lane&15)+16j
        int rbase = warp * 16 + (lane >> 4) * 8;
        int cbase = lane & 15;
        int acc[8][8];
#pragma unroll
        for (int r = 0; r < 8; r++)
#pragma unroll
            for (int j = 0; j < 8; j++) acc[r][j] = 0;

        load_stage(0, 0);
        for (int st = 0; st < NSt; st++) {
            if (st + 1 < NSt) {
                load_stage((st + 1) & 1, (st + 1) << 6);
                asm volatile("cp.async.wait_group 1;" ::: "memory");
            } else {
                asm volatile("cp.async.wait_group 0;" ::: "memory");
            }
            __syncthreads();
            const int8_t* gA = smem_gen + (st & 1 ? 8192 : 0);
            const int8_t* gB = smem_gen + 16384 + (st & 1 ? 8192 : 0);
#pragma unroll
            for (int c = 0; c < 4; c++) {
                int4 af[8];
#pragma unroll
                for (int r = 0; r < 8; r++)
                    af[r] = *(const int4*)(gA + swz(rbase + r, c));
#pragma unroll
                for (int j = 0; j < 8; j++) {
                    int4 bf = *(const int4*)(gB + swz(cbase + 16 * j, c));
#pragma unroll
                    for (int r = 0; r < 8; r++) {
                        int t = acc[r][j];
                        t = __dp4a(af[r].x, bf.x, t);
                        t = __dp4a(af[r].y, bf.y, t);
                        t = __dp4a(af[r].z, bf.z, t);
                        t = __dp4a(af[r].w, bf.w, t);
                        acc[r][j] = t;
                    }
                }
            }
            __syncthreads();
        }
        // stage C into smem (same swizzled layout as IMMA flavor)
#pragma unroll
        for (int r = 0; r < 8; r++) {
            int ra = rbase + r;
#pragma unroll
            for (int j = 0; j < 8; j++) {
                int ca = cbase + 16 * j;
                int chs = (((ca >> 2) ^ (ra & 7)) << 2) | (ca & 3);
                Cst[ra * 128 + chs] = acc[r][j];
            }
        }
        __syncthreads();
    }

    // ---------------- common coalesced epilogue ----------------
    float sc, invq = 0.f, inv7 = 0.f;
    int8_t* qkvbase = nullptr;
    if (EPI == 0) {
        int part = n0 / DIM;
        sc = actS[4] * wS[0];
        invq = 1.f / actS[part];
        qkvbase = (part == 0) ? g_q8 : (part == 1) ? g_k8 : g_v8;
    } else if (EPI == 1) sc = actS[5] * wS[1];
    else if (EPI == 2)   { sc = actS[6] * wS[2]; inv7 = 1.f / actS[7]; }
    else                 sc = actS[7] * wS[3];

    int n = n0 + lane * 4;
    float4 bv = *(const float4*)(bias + n);
    int head = 0, d0 = 0;
    if (EPI == 0) { head = (n % DIM) / HD; d0 = n % HD; }

#pragma unroll 4
    for (int rr = 0; rr < 16; rr++) {
        int r = warp * 16 + rr;
        int m = m0 + r;
        if (m >= M) break;
        int4 a4 = *(const int4*)&Cst[r * 128 + ((lane ^ (r & 7)) << 2)];
        float f0 = sc * (float)a4.x + bv.x;
        float f1 = sc * (float)a4.y + bv.y;
        float f2 = sc * (float)a4.z + bv.z;
        float f3 = sc * (float)a4.w + bv.w;
        if (EPI == 0) {
            int bwn = m / NT, tok = m % NT;
            uint32_t p = pack4(qint(f0, invq), qint(f1, invq), qint(f2, invq), qint(f3, invq));
            *(uint32_t*)(qkvbase + ((size_t)(bwn * NHEAD + head) * NT + tok) * HD + d0) = p;
        } else if (EPI == 1) {
            int bwn = m / NT, tok = m % NT;
            int bi = bwn / 25, wy = (bwn % 25) / 5, wx = bwn % 5;
            int gy = wy * WS + tok / WS, gx = wx * WS + tok % WS;
            if (gy < HH && gx < WW) {
                size_t off = (((size_t)bi * HH + gy) * WW + gx) * DIM + n;
                float4 xv = *(const float4*)(xin + off);
                *(float4*)(g_x2 + off) = make_float4(xv.x + f0, xv.y + f1, xv.z + f2, xv.w + f3);
            }
        } else if (EPI == 2) {
            float g0 = 0.5f * f0 * (1.0f + erff(f0 * 0.70710678118654752f));
            float g1 = 0.5f * f1 * (1.0f + erff(f1 * 0.70710678118654752f));
            float g2 = 0.5f * f2 * (1.0f + erff(f2 * 0.70710678118654752f));
            float g3 = 0.5f * f3 * (1.0f + erff(f3 * 0.70710678118654752f));
            *(uint32_t*)(g_g8 + (size_t)m * MLP + n) =
                pack4(qint(g0, inv7), qint(g1, inv7), qint(g2, inv7), qint(g3, inv7));
        } else {
            size_t off = (size_t)m * DIM + n;
            float4 xv = *(const float4*)(g_x2 + off);
            *(float4*)(outf + off) = make_float4(xv.x + f0, xv.y + f1, xv.z + f2, xv.w + f3);
        }
    }
}

// ---------------- fused window attention (dp4a, smem-resident) ----------------
__global__ __launch_bounds__(256) void attn_kernel(const float* __restrict__ rph,
                                                   const float* __restrict__ rpw,
                                                   const float* __restrict__ actS) {
    int bh = blockIdx.x;
    int bw = bh / NHEAD, head = bh % NHEAD;
    int tid = threadIdx.x;
    int warp = tid >> 5, lane = tid & 31;

    __shared__ int   sq[NT * 16];     // [tok][word]  q int8 rows
    __shared__ int   skw[16 * NT];    // [word][tok]  k transposed by word
    __shared__ int   svw[HD * 49];    // [d][tok/4]   v transposed (bytes [d][196])
    __shared__ float srow[8 * NT];    // per-warp score row
    __shared__ int   sattn[8 * 49];   // per-warp quantized attn row
    __shared__ float sbias[8 * 28];   // per-warp rel_h[0..13], rel_w[0..13]

    const int* qg = (const int*)g_q8 + (size_t)bh * 3136;
    const int* kg = (const int*)g_k8 + (size_t)bh * 3136;
    const int* vg = (const int*)g_v8 + (size_t)bh * 3136;
    int8_t* svb = (int8_t*)svw;
    for (int i = tid; i < 3136; i += 256) {
        sq[i] = qg[i];
        int tok = i >> 4, w = i & 15;
        skw[w * NT + tok] = kg[i];
        uint32_t vv = (uint32_t)vg[i];
        int d0 = 4 * w;
        svb[(d0 + 0) * NT + tok] = (int8_t)(vv & 0xff);
        svb[(d0 + 1) * NT + tok] = (int8_t)((vv >> 8) & 0xff);
        svb[(d0 + 2) * NT + tok] = (int8_t)((vv >> 16) & 0xff);
        svb[(d0 + 3) * NT + tok] = (int8_t)((vv >> 24) & 0xff);
    }
    __syncthreads();

    float a0 = actS[0], a1 = actS[1], a2 = actS[2], a3 = actS[3], a5 = actS[5];
    float qks = a0 * a1 * 0.125f;       // a0*a1*HD^-0.5
    float pvs = a3 * a2;
    float inv3 = 1.f / a3, inv5 = 1.f / a5;

    for (int q = warp; q < NT; q += 8) {
        int qi = q / WS, qj = q % WS;
        int qrow[16];
#pragma unroll
        for (int w = 0; w < 16; w++) qrow[w] = sq[q * 16 + w];

        // --- decomposed rel-pos bias: 28 dot products of length 64 ---
        const float* rp = nullptr; int slot = -1;
        if (lane < 14)                    { rp = rph + (qi - lane + 13) * HD;        slot = lane; }
        else if (lane >= 16 && lane < 30) { rp = rpw + (qj - (lane - 16) + 13) * HD; slot = 14 + lane - 16; }
        if (rp) {
            const float4* rp4 = (const float4*)rp;
            float bsum = 0.f;
#pragma unroll
            for (int w = 0; w < 16; w++) {
                float4 rv = rp4[w];
                int qv = qrow[w];
                bsum += (float)((qv << 24) >> 24) * rv.x
                      + (float)((qv << 16) >> 24) * rv.y
                      + (float)((qv << 8)  >> 24) * rv.z
                      + (float)( qv        >> 24) * rv.w;
            }
            sbias[warp * 28 + slot] = bsum * a0;
        }
        __syncwarp();

        // --- scores ---
        float lmax = -1e30f;
        for (int k = lane; k < NT; k += 32) {
            int acc = 0;
#pragma unroll
            for (int w = 0; w < 16; w++) acc = __dp4a(qrow[w], skw[w * NT + k], acc);
            float s = qks * (float)acc + sbias[warp * 28 + k / WS] + sbias[warp * 28 + 14 + k % WS];
            srow[warp * NT + k] = s;
            lmax = fmaxf(lmax, s);
        }
#pragma unroll
        for (int o = 16; o > 0; o >>= 1) lmax = fmaxf(lmax, __shfl_xor_sync(0xffffffff, lmax, o));

        // --- softmax + fake-quant(a3) ---
        float lsum = 0.f;
        for (int k = lane; k < NT; k += 32) {
            float e = __expf(srow[warp * NT + k] - lmax);
            srow[warp * NT + k] = e;
            lsum += e;
        }
#pragma unroll
        for (int o = 16; o > 0; o >>= 1) lsum += __shfl_xor_sync(0xffffffff, lsum, o);
        float invs = 1.f / lsum;
        int8_t* ab = (int8_t*)&sattn[warp * 49];
        for (int k = lane; k < NT; k += 32)
            ab[k] = (int8_t)qint(srow[warp * NT + k] * invs, inv3);
        __syncwarp();

        // --- P @ V (int8) + quantize(a5) ---
        for (int d = lane; d < HD; d += 32) {
            int acc = 0;
#pragma unroll
            for (int t = 0; t < 49; t++) acc = __dp4a(sattn[warp * 49 + t], svw[d * 49 + t], acc);
            float o = pvs * (float)acc;
            g_ao8[((size_t)bw * NT + q) * DIM + head * HD + d] = (int8_t)qint(o, inv5);
        }
        __syncwarp();
    }
}

// ---------------- launch ----------------
extern "C" void kernel_launch(void* const* d_in, const int* in_sizes, int n_in,
                              void* d_out, int out_size) {
    const float* x     = (const float*)d_in[0];
    const float* ln1w  = (const float*)d_in[1];
    const float* ln1b  = (const float*)d_in[2];
    const float* ln2w  = (const float*)d_in[3];
    const float* ln2b  = (const float*)d_in[4];
    const float* qkvw  = (const float*)d_in[5];
    const float* qkvb  = (const float*)d_in[6];
    const float* projw = (const float*)d_in[7];
    const float* projb = (const float*)d_in[8];
    const float* l1w   = (const float*)d_in[9];
    const float* l1b   = (const float*)d_in[10];
    const float* l2w   = (const float*)d_in[11];
    const float* l2b   = (const float*)d_in[12];
    const float* rph   = (const float*)d_in[13];
    const float* rpw   = (const float*)d_in[14];
    const float* actS  = (const float*)d_in[15];
    const float* wSc   = (const float*)d_in[16];
    float* out = (float*)d_out;

    const int SMEM_GEMM = 66560;  // 64KB (stages + C staging) + 1KB alignment slack
    static bool attr_done = false;
    if (!attr_done) {
        cudaFuncSetAttribute(gemm_tf<0>, cudaFuncAttributeMaxDynamicSharedMemorySize, SMEM_GEMM);
        cudaFuncSetAttribute(gemm_tf<1>, cudaFuncAttributeMaxDynamicSharedMemorySize, SMEM_GEMM);
        cudaFuncSetAttribute(gemm_tf<2>, cudaFuncAttributeMaxDynamicSharedMemorySize, SMEM_GEMM);
        cudaFuncSetAttribute(gemm_tf<3>, cudaFuncAttributeMaxDynamicSharedMemorySize, SMEM_GEMM);
        attr_done = true;
    }

    // quantize weights (per-launch; no caching allowed)
    quantw_a<<<460, 256>>>(qkvw, projw, wSc);
    quantw_b<<<460, 256>>>(l1w, l2w, wSc);

    // LN1 + window partition + quant(a4)
    ln_kernel<0><<<(TOK + 7) / 8, 256>>>(x, ln1w, ln1b, actS);

    // QKV: [19600 x 768] @ [2304 x 768]^T
    gemm_tf<0><<<dim3(2304 / 128, (TOK + 127) / 128), 256, SMEM_GEMM>>>(
        TOK, 3 * DIM, DIM, actS, wSc, qkvb, nullptr, nullptr);

    // attention per (window, head)
    attn_kernel<<<BHD, 256>>>(rph, rpw, actS);

    // proj: [19600 x 768] @ [768 x 768]^T + un-window + residual -> g_x2
    gemm_tf<1><<<dim3(DIM / 128, (TOK + 127) / 128), 256, SMEM_GEMM>>>(
        TOK, DIM, DIM, actS, wSc, projb, x, nullptr);

    // LN2 + quant(a6)
    ln_kernel<1><<<MTOK / 8, 256>>>(nullptr, ln2w, ln2b, actS);

    // lin1: [16384 x 768] @ [3072 x 768]^T + gelu + quant(a7)
    gemm_tf<2><<<dim3(MLP / 128, MTOK / 128), 256, SMEM_GEMM>>>(
        MTOK, MLP, DIM, actS, wSc, l1b, nullptr, nullptr);

    // lin2: [16384 x 3072] @ [768 x 3072]^T + residual -> out
    gemm_tf<3><<<dim3(DIM / 128, MTOK / 128), 256, SMEM_GEMM>>>(
        MTOK, DIM, MLP, actS, wSc, l2b, nullptr, out);
}

// round 14
// speedup vs baseline: 1.5584x; 1.5584x over previous
#include <cuda_runtime.h>
#include <cstdint>
#include <math.h>

// ---------------- problem constants ----------------
#define BATCH 4
#define HH 64
#define WW 64
#define DIM 768
#define NHEAD 12
#define HD 64
#define MLP 3072
#define WS 14
#define NT 196              // tokens per window (14*14)
#define NWIN 100            // windows: 4 * 5 * 5
#define TOK (NWIN*NT)       // 19600 window tokens
#define BHD (NWIN*NHEAD)    // 1200 (window, head) pairs
#define MTOK (BATCH*HH*WW)  // 16384 image tokens

#define MTILE 192           // hybrid GEMM M tile: 128 IMMA + 64 dp4a rows

// ---------------- device scratch (no dynamic alloc allowed) ----------------
__device__ int8_t g_qa  [TOK*DIM];        // quantized LN1 output (windowed), scale a4
__device__ int8_t g_wqkv[3*DIM*DIM];      // quantized weights
__device__ int8_t g_wproj[DIM*DIM];
__device__ int8_t g_wl1 [MLP*DIM];
__device__ int8_t g_wl2 [DIM*MLP];
__device__ int8_t g_q8  [BHD*NT*HD];      // [bh][tok][d], scale a0
__device__ int8_t g_k8  [BHD*NT*HD];      // [bh][tok][d], scale a1
__device__ int8_t g_v8  [BHD*NT*HD];      // [bh][tok][d], scale a2 (row-major)
__device__ int8_t g_ao8 [TOK*DIM];        // attention output, quantized scale a5
__device__ float  g_x2  [MTOK*DIM];       // x + attn branch (residual 1)
__device__ int8_t g_y8  [MTOK*DIM];       // quantized LN2 output, scale a6
__device__ int8_t g_g8  [MTOK*MLP];       // quantized GELU output, scale a7

// ---------------- helpers ----------------
__device__ __forceinline__ int qint(float x, float inv) {
    float r = rintf(x * inv);
    r = fminf(fmaxf(r, -128.f), 127.f);
    return (int)r;
}

__device__ __forceinline__ uint32_t pack4(int a, int b, int c, int d) {
    return (uint32_t)(uint8_t)(int8_t)a | ((uint32_t)(uint8_t)(int8_t)b << 8)
         | ((uint32_t)(uint8_t)(int8_t)c << 16) | ((uint32_t)(uint8_t)(int8_t)d << 24);
}

__device__ __forceinline__ void ldsm4(uint32_t& r0, uint32_t& r1, uint32_t& r2, uint32_t& r3,
                                      uint32_t addr) {
    asm volatile("ldmatrix.sync.aligned.m8n8.x4.shared.b16 {%0,%1,%2,%3}, [%4];"
                 : "=r"(r0), "=r"(r1), "=r"(r2), "=r"(r3) : "r"(addr));
}

__device__ __forceinline__ void mma_s8(int* c, const uint32_t* a, uint32_t b0, uint32_t b1) {
    asm volatile("mma.sync.aligned.m16n8k32.row.col.s32.s8.s8.s32 "
                 "{%0,%1,%2,%3}, {%4,%5,%6,%7}, {%8,%9}, {%0,%1,%2,%3};"
                 : "+r"(c[0]), "+r"(c[1]), "+r"(c[2]), "+r"(c[3])
                 : "r"(a[0]), "r"(a[1]), "r"(a[2]), "r"(a[3]), "r"(b0), "r"(b1));
}

__device__ __forceinline__ void cpasync16(uint32_t dst, const void* src) {
    asm volatile("cp.async.cg.shared.global [%0], [%1], 16;" :: "r"(dst), "l"(src) : "memory");
}

// swizzled smem offset for a row-of-64B tile; c = 16B chunk 0..3
__device__ __forceinline__ uint32_t swz(int row, int c) {
    return (uint32_t)(row * 64 + ((c ^ ((row >> 1) & 3)) << 4));
}

// ---------------- weight quantization ----------------
__global__ __launch_bounds__(256) void quantw_a(const float* __restrict__ qkvw,
                                                const float* __restrict__ projw,
                                                const float* __restrict__ wS) {
    const int B0 = 442368, B1 = 589824;
    float i0 = 1.f / wS[0], i1 = 1.f / wS[1];
    for (int idx = blockIdx.x * blockDim.x + threadIdx.x; idx < B1; idx += gridDim.x * blockDim.x) {
        const float* src; uint32_t* dst; float inv; int off;
        if (idx < B0) { off = idx;      src = qkvw;  dst = (uint32_t*)g_wqkv;  inv = i0; }
        else          { off = idx - B0; src = projw; dst = (uint32_t*)g_wproj; inv = i1; }
        float4 v = ((const float4*)src)[off];
        dst[off] = pack4(qint(v.x, inv), qint(v.y, inv), qint(v.z, inv), qint(v.w, inv));
    }
}

__global__ __launch_bounds__(256) void quantw_b(const float* __restrict__ l1w,
                                                const float* __restrict__ l2w,
                                                const float* __restrict__ wS) {
    const int B0 = 589824, B1 = 1179648;
    float i2 = 1.f / wS[2], i3 = 1.f / wS[3];
    for (int idx = blockIdx.x * blockDim.x + threadIdx.x; idx < B1; idx += gridDim.x * blockDim.x) {
        const float* src; uint32_t* dst; float inv; int off;
        if (idx < B0) { off = idx;      src = l1w; dst = (uint32_t*)g_wl1; inv = i2; }
        else          { off = idx - B0; src = l2w; dst = (uint32_t*)g_wl2; inv = i3; }
        float4 v = ((const float4*)src)[off];
        dst[off] = pack4(qint(v.x, inv), qint(v.y, inv), qint(v.z, inv), qint(v.w, inv));
    }
}

// ---------------- warp-per-row LayerNorm + quantize ----------------
template <int MODE>
__global__ __launch_bounds__(256) void ln_kernel(const float* __restrict__ x,
                                                 const float* __restrict__ w,
                                                 const float* __restrict__ b,
                                                 const float* __restrict__ actS) {
    int row = blockIdx.x * 8 + (threadIdx.x >> 5);
    int lane = threadIdx.x & 31;
    const float* src;
    uint32_t* orow;
    if (MODE == 0) {
        if (row >= TOK) return;
        int bw = row / NT, tok = row % NT;
        int bi = bw / 25, wy = (bw % 25) / 5, wx = bw % 5;
        int gy = wy * WS + tok / WS, gx = wx * WS + tok % WS;
        orow = (uint32_t*)(g_qa + (size_t)row * DIM);
        if (gy >= HH || gx >= WW) {
#pragma unroll
            for (int i = 0; i < 6; i++) orow[lane + 32 * i] = 0;
            return;
        }
        src = x + (((size_t)bi * HH + gy) * WW + gx) * DIM;
    } else {
        if (row >= MTOK) return;
        src = g_x2 + (size_t)row * DIM;
        orow = (uint32_t*)(g_y8 + (size_t)row * DIM);
    }

    const float4* s4 = (const float4*)src;
    float4 v[6];
    float sum = 0.f;
#pragma unroll
    for (int i = 0; i < 6; i++) {
        v[i] = s4[lane + 32 * i];
        sum += v[i].x + v[i].y + v[i].z + v[i].w;
    }
#pragma unroll
    for (int o = 16; o > 0; o >>= 1) sum += __shfl_xor_sync(0xffffffff, sum, o);
    float mu = sum * (1.f / DIM);
    float s2 = 0.f;
#pragma unroll
    for (int i = 0; i < 6; i++) {
        float dx = v[i].x - mu, dy = v[i].y - mu, dz = v[i].z - mu, dw = v[i].w - mu;
        s2 += dx * dx + dy * dy + dz * dz + dw * dw;
    }
#pragma unroll
    for (int o = 16; o > 0; o >>= 1) s2 += __shfl_xor_sync(0xffffffff, s2, o);
    float rstd = rsqrtf(s2 * (1.f / DIM) + 1e-6f);
    float inv = 1.f / actS[MODE == 0 ? 4 : 6];
    const float4* w4 = (const float4*)w;
    const float4* b4 = (const float4*)b;
#pragma unroll
    for (int i = 0; i < 6; i++) {
        float4 wv = w4[lane + 32 * i], bv = b4[lane + 32 * i];
        orow[lane + 32 * i] = pack4(qint((v[i].x - mu) * rstd * wv.x + bv.x, inv),
                                    qint((v[i].y - mu) * rstd * wv.y + bv.y, inv),
                                    qint((v[i].z - mu) * rstd * wv.z + bv.z, inv),
                                    qint((v[i].w - mu) * rstd * wv.w + bv.w, inv));
    }
}

// ---------------- hybrid GEMM: IMMA warps (rows 0-127) + dp4a warps (rows 128-191) ----------------
// C = A @ B^T. block tile 192x128x64B. 512 threads: warps 0-7 IMMA, warps 8-15 dp4a.
// dp4a accumulators live in smem (32KB), rmw once per K stage.  (verified R10 kernel)
template <int EPI>
__global__ __launch_bounds__(512, 1) void gemm_hyb(int M, int N, int K,
                                                   const float* __restrict__ actS,
                                                   const float* __restrict__ wS,
                                                   const float* __restrict__ bias,
                                                   const float* __restrict__ xin,
                                                   float* __restrict__ outf) {
    const int8_t* Aptr;
    const int8_t* Bptr;
    if (EPI == 0)      { Aptr = g_qa;  Bptr = g_wqkv;  }
    else if (EPI == 1) { Aptr = g_ao8; Bptr = g_wproj; }
    else if (EPI == 2) { Aptr = g_y8;  Bptr = g_wl1;   }
    else               { Aptr = g_g8;  Bptr = g_wl2;   }

    extern __shared__ int8_t dsm_raw[];
    uint32_t raw32 = (uint32_t)__cvta_generic_to_shared(dsm_raw);
    uint32_t sbase = (raw32 + 1023u) & ~1023u;
    int8_t* smem_gen = dsm_raw + (sbase - raw32);

    uint32_t sA[2] = { sbase,          sbase + 12288 };
    uint32_t sB[2] = { sbase + 24576,  sbase + 32768 };
    int* dac = (int*)(smem_gen + 65536);

    int tid = threadIdx.x;
    int warp = tid >> 5, lane = tid & 31;
    int wm = (warp & 1) * 64;              // IMMA warp m offset
    int wn = (warp >> 1) * 32;             // IMMA warp n offset
    int w8 = warp - 8;                     // dp4a warp index
    int m0 = blockIdx.y * MTILE, n0 = blockIdx.x * 128;

    int acc[4][4][4];
#pragma unroll
    for (int mi = 0; mi < 4; mi++)
#pragma unroll
        for (int ni = 0; ni < 4; ni++)
#pragma unroll
            for (int r = 0; r < 4; r++) acc[mi][ni][r] = 0;

    if (warp >= 8) {
#pragma unroll
        for (int r = 0; r < 8; r++)
#pragma unroll
            for (int j = 0; j < 4; j++)
                dac[(w8 * 8 + r) * 128 + lane + 32 * j] = 0;
    }

    const int NSt = K >> 6;

    auto load_stage = [&](int s, int k0) {
#pragma unroll
        for (int i = 0; i < 3; i++) {
            int idx = tid + i * 512;
            if (idx < 768) {
                int row = idx >> 2, c = idx & 3;
                int rg = m0 + row; if (rg >= M) rg = M - 1;
                cpasync16(sA[s] + swz(row, c), Aptr + (size_t)rg * K + k0 + c * 16);
            } else if (idx < 1280) {
                int jdx = idx - 768;
                int row = jdx >> 2, c = jdx & 3;
                cpasync16(sB[s] + swz(row, c), Bptr + (size_t)(n0 + row) * K + k0 + c * 16);
            }
        }
        asm volatile("cp.async.commit_group;" ::: "memory");
    };

    load_stage(0, 0);

    for (int st = 0; st < NSt; st++) {
        if (st + 1 < NSt) {
            load_stage((st + 1) & 1, (st + 1) << 6);
            asm volatile("cp.async.wait_group 1;" ::: "memory");
        } else {
            asm volatile("cp.async.wait_group 0;" ::: "memory");
        }
        __syncthreads();

        int s = st & 1;
        if (warp < 8) {
#pragma unroll
            for (int ks = 0; ks < 2; ks++) {
                uint32_t a[4][4];
#pragma unroll
                for (int mi = 0; mi < 4; mi++) {
                    int r = wm + mi * 16 + (lane & 15);
                    int c = ks * 2 + (lane >> 4);
                    ldsm4(a[mi][0], a[mi][1], a[mi][2], a[mi][3], sA[s] + swz(r, c));
                }
                uint32_t bb[2][4];
#pragma unroll
                for (int nj = 0; nj < 2; nj++) {
                    int rn = wn + nj * 16 + (lane & 7) + ((lane >> 1) & 8);
                    int c = ks * 2 + ((lane >> 3) & 1);
                    ldsm4(bb[nj][0], bb[nj][1], bb[nj][2], bb[nj][3], sB[s] + swz(rn, c));
                }
#pragma unroll
                for (int mi = 0; mi < 4; mi++)
#pragma unroll
                    for (int ni = 0; ni < 4; ni++)
                        mma_s8(acc[mi][ni], a[mi], bb[ni >> 1][(ni & 1) * 2], bb[ni >> 1][(ni & 1) * 2 + 1]);
            }
        } else {
            const int8_t* gA = smem_gen + (s ? 12288 : 0);
            const int8_t* gB = smem_gen + 24576 + (s ? 8192 : 0);
#pragma unroll
            for (int rh = 0; rh < 2; rh++) {
                int arow = 128 + w8 * 8 + rh * 4;
                int t16[4][4];
#pragma unroll
                for (int r = 0; r < 4; r++)
#pragma unroll
                    for (int j = 0; j < 4; j++) t16[r][j] = 0;
#pragma unroll
                for (int c = 0; c < 4; c++) {
                    int4 bfr[4];
#pragma unroll
                    for (int j = 0; j < 4; j++)
                        bfr[j] = *(const int4*)(gB + swz(lane + 32 * j, c));
#pragma unroll
                    for (int r = 0; r < 4; r++) {
                        int4 af = *(const int4*)(gA + swz(arow + r, c));
#pragma unroll
                        for (int j = 0; j < 4; j++) {
                            int t = t16[r][j];
                            t = __dp4a(af.x, bfr[j].x, t);
                            t = __dp4a(af.y, bfr[j].y, t);
                            t = __dp4a(af.z, bfr[j].z, t);
                            t = __dp4a(af.w, bfr[j].w, t);
                            t16[r][j] = t;
                        }
                    }
                }
#pragma unroll
                for (int r = 0; r < 4; r++)
#pragma unroll
                    for (int j = 0; j < 4; j++)
                        dac[(w8 * 8 + rh * 4 + r) * 128 + lane + 32 * j] += t16[r][j];
            }
        }
        __syncthreads();
    }

    float sc, invq = 0.f, inv7 = 0.f;
    int8_t* qkvbase = nullptr;
    if (EPI == 0) {
        int part = n0 / DIM;
        sc = actS[4] * wS[0];
        invq = 1.f / actS[part];
        qkvbase = (part == 0) ? g_q8 : (part == 1) ? g_k8 : g_v8;
    } else if (EPI == 1) sc = actS[5] * wS[1];
    else if (EPI == 2)   { sc = actS[6] * wS[2]; inv7 = 1.f / actS[7]; }
    else                 sc = actS[7] * wS[3];

    if (warp < 8) {
        int* Cst = (int*)smem_gen;
#pragma unroll
        for (int mi = 0; mi < 4; mi++) {
            int r = wm + mi * 16 + (lane >> 2);
#pragma unroll
            for (int ni = 0; ni < 4; ni++) {
                int c = wn + ni * 8 + (lane & 3) * 2;
                int chs = (((c >> 2) ^ (r & 7)) << 2) | (c & 3);
                *(int2*)&Cst[r * 128 + chs]       = make_int2(acc[mi][ni][0], acc[mi][ni][1]);
                *(int2*)&Cst[(r + 8) * 128 + chs] = make_int2(acc[mi][ni][2], acc[mi][ni][3]);
            }
        }
        asm volatile("bar.sync 1, 256;" ::: "memory");

        int n = n0 + lane * 4;
        float4 bv = *(const float4*)(bias + n);
        int head = 0, d0 = 0;
        if (EPI == 0) { head = (n % DIM) / HD; d0 = n % HD; }

#pragma unroll 4
        for (int rr = 0; rr < 16; rr++) {
            int r = warp * 16 + rr;
            int m = m0 + r;
            if (m >= M) break;
            int4 a4 = *(const int4*)&Cst[r * 128 + ((lane ^ (r & 7)) << 2)];
            float f0 = sc * (float)a4.x + bv.x;
            float f1 = sc * (float)a4.y + bv.y;
            float f2 = sc * (float)a4.z + bv.z;
            float f3 = sc * (float)a4.w + bv.w;
            if (EPI == 0) {
                int bwn = m / NT, tok = m % NT;
                uint32_t p = pack4(qint(f0, invq), qint(f1, invq), qint(f2, invq), qint(f3, invq));
                *(uint32_t*)(qkvbase + ((size_t)(bwn * NHEAD + head) * NT + tok) * HD + d0) = p;
            } else if (EPI == 1) {
                int bwn = m / NT, tok = m % NT;
                int bi = bwn / 25, wy = (bwn % 25) / 5, wx = bwn % 5;
                int gy = wy * WS + tok / WS, gx = wx * WS + tok % WS;
                if (gy < HH && gx < WW) {
                    size_t off = (((size_t)bi * HH + gy) * WW + gx) * DIM + n;
                    float4 xv = *(const float4*)(xin + off);
                    *(float4*)(g_x2 + off) = make_float4(xv.x + f0, xv.y + f1, xv.z + f2, xv.w + f3);
                }
            } else if (EPI == 2) {
                float g0 = 0.5f * f0 * (1.0f + erff(f0 * 0.70710678118654752f));
                float g1 = 0.5f * f1 * (1.0f + erff(f1 * 0.70710678118654752f));
                float g2 = 0.5f * f2 * (1.0f + erff(f2 * 0.70710678118654752f));
                float g3 = 0.5f * f3 * (1.0f + erff(f3 * 0.70710678118654752f));
                *(uint32_t*)(g_g8 + (size_t)m * MLP + n) =
                    pack4(qint(g0, inv7), qint(g1, inv7), qint(g2, inv7), qint(g3, inv7));
            } else {
                size_t off = (size_t)m * DIM + n;
                float4 xv = *(const float4*)(g_x2 + off);
                *(float4*)(outf + off) = make_float4(xv.x + f0, xv.y + f1, xv.z + f2, xv.w + f3);
            }
        }
    } else {
        float bj[4];
        int cbase = n0 % DIM;
#pragma unroll
        for (int j = 0; j < 4; j++) bj[j] = bias[n0 + lane + 32 * j];
#pragma unroll
        for (int r = 0; r < 8; r++) {
            int m = m0 + 128 + w8 * 8 + r;
            if (m >= M) break;
            int bwn = 0, tok = 0;
            size_t xoff = 0;
            bool valid = true;
            if (EPI == 0) { bwn = m / NT; tok = m % NT; }
            else if (EPI == 1) {
                bwn = m / NT; tok = m % NT;
                int bi = bwn / 25, wy = (bwn % 25) / 5, wx = bwn % 5;
                int gy = wy * WS + tok / WS, gx = wx * WS + tok % WS;
                valid = (gy < HH && gx < WW);
                if (valid) xoff = (((size_t)bi * HH + gy) * WW + gx) * DIM;
            }
#pragma unroll
            for (int j = 0; j < 4; j++) {
                int a = dac[(w8 * 8 + r) * 128 + lane + 32 * j];
                float f = sc * (float)a + bj[j];
                int coll = lane + 32 * j;
                if (EPI == 0) {
                    int hh = cbase + coll;
                    int head = hh >> 6, d = hh & 63;
                    qkvbase[((size_t)(bwn * NHEAD + head) * NT + tok) * HD + d] = (int8_t)qint(f, invq);
                } else if (EPI == 1) {
                    if (valid) {
                        size_t off = xoff + n0 + coll;
                        g_x2[off] = xin[off] + f;
                    }
                } else if (EPI == 2) {
                    float g = 0.5f * f * (1.0f + erff(f * 0.70710678118654752f));
                    g_g8[(size_t)m * MLP + n0 + coll] = (int8_t)qint(g, inv7);
                } else {
                    size_t off = (size_t)m * DIM + n0 + coll;
                    outf[off] = g_x2[off] + f;
                }
            }
        }
    }
}

// ---------------- fused window attention: vectorized dp4a ----------------
// 256 threads = 8 warps; warp processes one q at a time (q = warp + 8*t).
// K rows stride 20 words, V^T rows stride 52 words -> conflict-free LDS.128.
__global__ __launch_bounds__(256, 4) void attn_kernel(const float* __restrict__ rph,
                                                      const float* __restrict__ rpw,
                                                      const float* __restrict__ actS) {
    int bh = blockIdx.x;
    int bw = bh / NHEAD, head = bh % NHEAD;
    int tid = threadIdx.x;
    int warp = tid >> 5, lane = tid & 31;

    __shared__ int   sq  [NT * 16];    // [tok][16w] q rows (stride 16)
    __shared__ int   sk  [NT * 20];    // [tok][20w] k rows (stride 20; 16 data + 4 pad)
    __shared__ int   svw [HD * 52];    // [d][52w] V^T bytes (cols 0..195 data, 196..207 zero)
    __shared__ int   sattn[8 * 52];    // per-warp quantized probs bytes (pad zeroed)
    __shared__ float sbias[8 * 28];    // per-warp rel_h[0..13], rel_w[0..13]
    __shared__ float qf  [8 * 64];     // per-warp float q vector

    const int4* qg4 = (const int4*)(g_q8 + (size_t)bh * 12544);
    const int4* kg4 = (const int4*)(g_k8 + (size_t)bh * 12544);
    const int*  vg  = (const int*)(g_v8 + (size_t)bh * 12544);

    // load q and k (vectorized); k with padded stride
    for (int i = tid; i < 784; i += 256) {
        int tok = i >> 2, w4 = i & 3;
        ((int4*)sq)[i] = qg4[i];
        *(int4*)(sk + tok * 20 + w4 * 4) = kg4[i];
    }
    // zero V^T and attn pads
    if (tid < 192) svw[(tid / 3) * 52 + 49 + (tid % 3)] = 0;
    if (tid < 24)  sattn[(tid / 3) * 52 + 49 + (tid % 3)] = 0;
    // transpose V bytes into svw
    int8_t* svb = (int8_t*)svw;
    for (int i = tid; i < 3136; i += 256) {
        int tok = i >> 4, w = i & 15;
        uint32_t vv = (uint32_t)vg[i];
        int d0 = 4 * w;
        svb[(d0 + 0) * 208 + tok] = (int8_t)(vv & 0xff);
        svb[(d0 + 1) * 208 + tok] = (int8_t)((vv >> 8) & 0xff);
        svb[(d0 + 2) * 208 + tok] = (int8_t)((vv >> 16) & 0xff);
        svb[(d0 + 3) * 208 + tok] = (int8_t)((vv >> 24) & 0xff);
    }
    __syncthreads();

    float a0 = actS[0], a1 = actS[1], a2 = actS[2], a3 = actS[3], a5 = actS[5];
    float qks = a0 * a1 * 0.125f;
    float pvs = a3 * a2;
    float inv3 = 1.f / a3, inv5 = 1.f / a5;

    // hoisted per-lane k decomposition (k = lane + 32c)
    int khh[7], kww[7];
#pragma unroll
    for (int c = 0; c < 7; c++) {
        int k = lane + 32 * c;
        int kc = (k < NT) ? k : 0;
        khh[c] = kc / WS;
        kww[c] = kc % WS;
    }

    for (int q = warp; q < NT; q += 8) {
        int qi = q / WS, qj = q % WS;

        // q row into registers (broadcast LDS.128)
        int qrow[16];
        {
            const int4* q4 = (const int4*)(sq + q * 16);
            int4 t0 = q4[0], t1 = q4[1], t2 = q4[2], t3 = q4[3];
            qrow[0]=t0.x; qrow[1]=t0.y; qrow[2]=t0.z; qrow[3]=t0.w;
            qrow[4]=t1.x; qrow[5]=t1.y; qrow[6]=t1.z; qrow[7]=t1.w;
            qrow[8]=t2.x; qrow[9]=t2.y; qrow[10]=t2.z; qrow[11]=t2.w;
            qrow[12]=t3.x; qrow[13]=t3.y; qrow[14]=t3.z; qrow[15]=t3.w;
        }
        // q as floats (2 bytes per lane, sign-extending LDS)
        {
            const int8_t* qb = (const int8_t*)sq + q * 64;
            qf[warp * 64 + 2 * lane]     = (float)qb[2 * lane];
            qf[warp * 64 + 2 * lane + 1] = (float)qb[2 * lane + 1];
        }
        __syncwarp();

        // --- decomposed rel-pos bias: 28 dot products of length 64 ---
        const float* rp = nullptr; int slot = 0;
        if (lane < 14)                    { rp = rph + (qi - lane + 13) * HD;        slot = lane; }
        else if (lane >= 16 && lane < 30) { rp = rpw + (qj - (lane - 16) + 13) * HD; slot = 14 + lane - 16; }
        if (rp) {
            const float4* rp4 = (const float4*)rp;
            const float* qfp = &qf[warp * 64];
            float bsum = 0.f;
#pragma unroll
            for (int w = 0; w < 16; w++) {
                float4 rv = rp4[w];
                bsum += qfp[4*w] * rv.x + qfp[4*w+1] * rv.y + qfp[4*w+2] * rv.z + qfp[4*w+3] * rv.w;
            }
            sbias[warp * 28 + slot] = bsum * a0;
        }
        __syncwarp();

        // --- scores (registers, vectorized K loads) ---
        float sreg[7];
        float lmax = -1e30f;
#pragma unroll
        for (int c = 0; c < 7; c++) {
            int k = lane + 32 * c;
            int kc = (k < NT) ? k : 0;
            const int4* krow = (const int4*)(sk + kc * 20);
            int acc = 0;
#pragma unroll
            for (int w = 0; w < 4; w++) {
                int4 kv = krow[w];
                acc = __dp4a(qrow[4*w],   kv.x, acc);
                acc = __dp4a(qrow[4*w+1], kv.y, acc);
                acc = __dp4a(qrow[4*w+2], kv.z, acc);
                acc = __dp4a(qrow[4*w+3], kv.w, acc);
            }
            float s = qks * (float)acc + sbias[warp * 28 + khh[c]] + sbias[warp * 28 + 14 + kww[c]];
            sreg[c] = s;
            if (k < NT) lmax = fmaxf(lmax, s);
        }
#pragma unroll
        for (int o = 16; o > 0; o >>= 1) lmax = fmaxf(lmax, __shfl_xor_sync(0xffffffff, lmax, o));

        // --- softmax (registers) ---
        float ee[7];
        float lsum = 0.f;
#pragma unroll
        for (int c = 0; c < 7; c++) {
            int k = lane + 32 * c;
            float e = (k < NT) ? __expf(sreg[c] - lmax) : 0.f;
            ee[c] = e;
            lsum += e;
        }
#pragma unroll
        for (int o = 16; o > 0; o >>= 1) lsum += __shfl_xor_sync(0xffffffff, lsum, o);
        float invs = 1.f / lsum;
        int8_t* ab = (int8_t*)&sattn[warp * 52];
#pragma unroll
        for (int c = 0; c < 7; c++) {
            int k = lane + 32 * c;
            if (k < NT) ab[k] = (int8_t)qint(ee[c] * invs, inv3);
        }
        __syncwarp();

        // --- P @ V: each lane owns d = lane and lane+32 ---
        int acc0 = 0, acc1 = 0;
        const int4* at4 = (const int4*)&sattn[warp * 52];
        const int4* v0  = (const int4*)&svw[lane * 52];
        const int4* v1  = (const int4*)&svw[(lane + 32) * 52];
#pragma unroll
        for (int j = 0; j < 13; j++) {
            int4 a4 = at4[j];
            int4 va = v0[j];
            acc0 = __dp4a(a4.x, va.x, acc0);
            acc0 = __dp4a(a4.y, va.y, acc0);
            acc0 = __dp4a(a4.z, va.z, acc0);
            acc0 = __dp4a(a4.w, va.w, acc0);
            int4 vb = v1[j];
            acc1 = __dp4a(a4.x, vb.x, acc1);
            acc1 = __dp4a(a4.y, vb.y, acc1);
            acc1 = __dp4a(a4.z, vb.z, acc1);
            acc1 = __dp4a(a4.w, vb.w, acc1);
        }
        int8_t* orow = g_ao8 + ((size_t)(bw * NT + q)) * DIM + head * HD;
        orow[lane]      = (int8_t)qint(pvs * (float)acc0, inv5);
        orow[lane + 32] = (int8_t)qint(pvs * (float)acc1, inv5);
        __syncwarp();
    }
}

// ---------------- launch ----------------
extern "C" void kernel_launch(void* const* d_in, const int* in_sizes, int n_in,
                              void* d_out, int out_size) {
    const float* x     = (const float*)d_in[0];
    const float* ln1w  = (const float*)d_in[1];
    const float* ln1b  = (const float*)d_in[2];
    const float* ln2w  = (const float*)d_in[3];
    const float* ln2b  = (const float*)d_in[4];
    const float* qkvw  = (const float*)d_in[5];
    const float* qkvb  = (const float*)d_in[6];
    const float* projw = (const float*)d_in[7];
    const float* projb = (const float*)d_in[8];
    const float* l1w   = (const float*)d_in[9];
    const float* l1b   = (const float*)d_in[10];
    const float* l2w   = (const float*)d_in[11];
    const float* l2b   = (const float*)d_in[12];
    const float* rph   = (const float*)d_in[13];
    const float* rpw   = (const float*)d_in[14];
    const float* actS  = (const float*)d_in[15];
    const float* wSc   = (const float*)d_in[16];
    float* out = (float*)d_out;

    const int SMEM_GEMM = 99328;  // 64KB C-staging + 32KB dacc + 1KB alignment slack
    static bool attr_done = false;
    if (!attr_done) {
        cudaFuncSetAttribute(gemm_hyb<0>, cudaFuncAttributeMaxDynamicSharedMemorySize, SMEM_GEMM);
        cudaFuncSetAttribute(gemm_hyb<1>, cudaFuncAttributeMaxDynamicSharedMemorySize, SMEM_GEMM);
        cudaFuncSetAttribute(gemm_hyb<2>, cudaFuncAttributeMaxDynamicSharedMemorySize, SMEM_GEMM);
        cudaFuncSetAttribute(gemm_hyb<3>, cudaFuncAttributeMaxDynamicSharedMemorySize, SMEM_GEMM);
        attr_done = true;
    }

    // quantize weights (per-launch; no caching allowed)
    quantw_a<<<460, 256>>>(qkvw, projw, wSc);
    quantw_b<<<460, 256>>>(l1w, l2w, wSc);

    // LN1 + window partition + quant(a4)
    ln_kernel<0><<<(TOK + 7) / 8, 256>>>(x, ln1w, ln1b, actS);

    // QKV: [19600 x 768] @ [2304 x 768]^T
    gemm_hyb<0><<<dim3(2304 / 128, (TOK + MTILE - 1) / MTILE), 512, SMEM_GEMM>>>(
        TOK, 3 * DIM, DIM, actS, wSc, qkvb, nullptr, nullptr);

    // attention per (window, head)
    attn_kernel<<<BHD, 256>>>(rph, rpw, actS);

    // proj: [19600 x 768] @ [768 x 768]^T + un-window + residual -> g_x2
    gemm_hyb<1><<<dim3(DIM / 128, (TOK + MTILE - 1) / MTILE), 512, SMEM_GEMM>>>(
        TOK, DIM, DIM, actS, wSc, projb, x, nullptr);

    // LN2 + quant(a6)
    ln_kernel<1><<<MTOK / 8, 256>>>(nullptr, ln2w, ln2b, actS);

    // lin1: [16384 x 768] @ [3072 x 768]^T + gelu + quant(a7)
    gemm_hyb<2><<<dim3(MLP / 128, (MTOK + MTILE - 1) / MTILE), 512, SMEM_GEMM>>>(
        MTOK, MLP, DIM, actS, wSc, l1b, nullptr, nullptr);

    // lin2: [16384 x 3072] @ [768 x 3072]^T + residual -> out
    gemm_hyb<3><<<dim3(DIM / 128, (MTOK + MTILE - 1) / MTILE), 512, SMEM_GEMM>>>(
        MTOK, DIM, MLP, actS, wSc, l2b, nullptr, out);
}